// round 10
// baseline (speedup 1.0000x reference)
#include <cuda_runtime.h>
#include <cstdint>

#define NL   28
#define DIM  1024
#define NH   16
#define HD   64
#define FFN  2816
#define VOCAB 32000
#define GRIDSZ 296

// ---------------- device scratch ----------------
__device__ float g_h[2][DIM];              // residual stream (atomically updated)
__device__ float g_qkv[2][2][3 * DIM];     // [parity][batch][q|k|v]
__device__ float g_gp[2][2][2][FFN];       // [parity][gate/up][batch][col]
__device__ float g_hn[2][DIM];             // final normed hidden

// ---------------- helpers ----------------
__device__ __forceinline__ float block_sum(float v) {
    __shared__ float sh[8];
    int lane = threadIdx.x & 31, w = threadIdx.x >> 5;
#pragma unroll
    for (int o = 16; o; o >>= 1) v += __shfl_xor_sync(0xffffffffu, v, o);
    __syncthreads();
    if (lane == 0) sh[w] = v;
    __syncthreads();
    float r = sh[0];
#pragma unroll
    for (int i = 1; i < 8; i++) r += sh[i];
    return r;
}

#define FMA8(w4, x0, x1)                                                   \
    a[0] += (x0) * (w4).x; a[1] += (x0) * (w4).y;                          \
    a[2] += (x0) * (w4).z; a[3] += (x0) * (w4).w;                          \
    a[4] += (x1) * (w4).x; a[5] += (x1) * (w4).y;                          \
    a[6] += (x1) * (w4).z; a[7] += (x1) * (w4).w;

// A tile = 64 cols x 128 rows. Thread (rr = t>>4, c4 = t&15) loads 8 float4.
struct Tile { const float* p; const float* x0; const float* x1; };

template<int LD>
__device__ __forceinline__ void load8(float4* w, const float* p) {
#pragma unroll
    for (int r = 0; r < 8; r++)
        w[r] = *(const float4*)(p + (size_t)(r * 16) * LD);
}

__device__ __forceinline__ void fma_tile(float* a, const float4* w,
                                         const Tile& T, int rr) {
#pragma unroll
    for (int r = 0; r < 8; r++) {
        int d = rr + r * 16;
        float x0 = T.x0[d], x1 = T.x1[d];
        FMA8(w[r], x0, x1);
    }
}

// reduce a[8] over the 16 row-threads per col-quad; reusable across tiles.
__device__ __forceinline__ bool tile_reduce(float* a, float& s, int& b, int& col) {
    __shared__ float red[8][16][8];
    int t = threadIdx.x, lane = t & 31, wid = t >> 5;
    __syncthreads();                       // protect red[] from previous tile's reads
#pragma unroll
    for (int j = 0; j < 8; j++) a[j] += __shfl_xor_sync(0xffffffffu, a[j], 16);
    if (lane < 16)
#pragma unroll
        for (int j = 0; j < 8; j++) red[wid][lane][j] = a[j];
    __syncthreads();
    if (t >= 128) return false;
    int c4 = t >> 3, j = t & 7;
    float acc = 0.f;
#pragma unroll
    for (int w = 0; w < 8; w++) acc += red[w][c4][j];
    s = acc; b = j >> 2; col = c4 * 4 + (j & 3);
    return true;
}

// grid-strided, double-buffered tile streamer.
template<int LD, class TF, class OF>
__device__ __forceinline__ void gemv_stream(int ntiles, const TF& tf, const OF& of) {
    float4 wA[8], wB[8];
    int rr = threadIdx.x >> 4;
    int tauA = blockIdx.x;
    if (tauA >= ntiles) return;
    Tile A = tf(tauA);
    load8<LD>(wA, A.p);
    for (;;) {
        int tauB = tauA + GRIDSZ;
        bool hasB = tauB < ntiles;
        Tile B;
        if (hasB) { B = tf(tauB); load8<LD>(wB, B.p); }
        {
            float a[8] = {0,0,0,0,0,0,0,0};
            fma_tile(a, wA, A, rr);
            float s; int b, col;
            if (tile_reduce(a, s, b, col)) of(tauA, s, b, col);
        }
        if (!hasB) break;
        int tauC = tauB + GRIDSZ;
        bool hasC = tauC < ntiles;
        if (hasC) { A = tf(tauC); load8<LD>(wA, A.p); }
        {
            float a[8] = {0,0,0,0,0,0,0,0};
            fma_tile(a, wB, B, rr);
            float s; int b, col;
            if (tile_reduce(a, s, b, col)) of(tauB, s, b, col);
        }
        if (!hasC) break;
        tauA = tauC;
    }
}

// rms prologue: xs[b][i] = rms(g_h[b]) * gamma[i]
__device__ __forceinline__ void rms_x(const float* __restrict__ gamma,
                                      float (*xs)[DIM]) {
    int t = threadIdx.x;
    float s0 = 0.f, s1 = 0.f;
    for (int i = t; i < DIM; i += 256) {
        float v0 = g_h[0][i], v1 = g_h[1][i];
        xs[0][i] = v0; xs[1][i] = v1;
        s0 += v0 * v0; s1 += v1 * v1;
    }
    s0 = block_sum(s0);
    s1 = block_sum(s1);
    float r0 = rsqrtf(s0 * (1.f / DIM) + 1e-5f);
    float r1 = rsqrtf(s1 * (1.f / DIM) + 1e-5f);
    for (int i = t; i < DIM; i += 256) {
        float g = gamma[i];
        xs[0][i] *= r0 * g;
        xs[1][i] *= r1 * g;
    }
    __syncthreads();
}

// ---------------- init ----------------
__global__ void k_init(const float* __restrict__ emb) {
    int i = blockIdx.x * blockDim.x + threadIdx.x;
    if (i < 2 * DIM) g_h[i / DIM][i % DIM] = emb[i];
    int z = i - 2 * DIM;
    if (z >= 0) {
        if (z < 2 * 3 * DIM)            ((float*)g_qkv[0])[z] = 0.f;
        else if (z < 2*3*DIM + 4*FFN)   ((float*)g_gp[0])[z - 2*3*DIM] = 0.f;
    }
}

// ---------------- K1: rms1 + QKV. 384 tiles -------------------------------
struct QkvTF {
    const float *wq, *wk, *wv;
    const float *xs0, *xs1;
    __device__ Tile operator()(int tau) const {
        int cg = tau % 48, ks = tau / 48;
        int e0 = cg * 64;
        const float* W = wq; int ec = e0;
        if (e0 >= 2 * DIM)    { W = wv; ec = e0 - 2 * DIM; }
        else if (e0 >= DIM)   { W = wk; ec = e0 - DIM; }
        int t = threadIdx.x;
        Tile T;
        T.p  = W + (size_t)(ks * 128 + (t >> 4)) * DIM + ec + 4 * (t & 15);
        T.x0 = xs0 + ks * 128;
        T.x1 = xs1 + ks * 128;
        return T;
    }
};
struct QkvOF {
    int par;
    __device__ void operator()(int tau, float s, int b, int col) const {
        int cg = tau % 48;
        atomicAdd(&g_qkv[par][b][cg * 64 + col], s);
    }
};
__global__ void __launch_bounds__(256, 2) k_qkv(const float* __restrict__ wq,
                                                const float* __restrict__ wk,
                                                const float* __restrict__ wv,
                                                const float* __restrict__ ln1,
                                                int par) {
    __shared__ float xs[2][DIM];
    rms_x(ln1, xs);
    QkvTF tf{wq, wk, wv, xs[0], xs[1]};
    QkvOF of{par};
    gemv_stream<DIM>(384, tf, of);
}

// ---------------- K2: RoPE + attn + O GEMV. grid 256 = 16cg x 16head ------
__global__ void __launch_bounds__(256, 2) k_attn(const float* __restrict__ wo,
                                                 const int* __restrict__ cpos,
                                                 int par) {
    __shared__ float xo[2][HD];
    int t = threadIdx.x, lane = t & 31, wid = t >> 5;
    int cg = blockIdx.x & 15, ks = blockIdx.x >> 4;   // ks = head
    int rr = t >> 4, c4 = t & 15;

    if (blockIdx.x < 16) {
        float* z = (float*)g_qkv[par ^ 1] + blockIdx.x * 384;
        for (int i = t; i < 384; i += 256) z[i] = 0.f;
    }

    if (wid < 2) {
        int b = wid;
        const float* q = &g_qkv[par][b][ks * HD];
        const float* k = &g_qkv[par][b][DIM + ks * HD];
        const float* v = &g_qkv[par][b][2 * DIM + ks * HD];
        int pos = cpos[0];
        float inv_freq = __expf(-(float)(2 * lane) * (1.f / HD) * logf(10000.f));
        float ang = (float)pos * inv_freq;
        float cs = cosf(ang), sn = sinf(ang);
        float q1 = q[lane], q2 = q[lane + 32];
        float k1 = k[lane], k2 = k[lane + 32];
        float q1r = q1 * cs - q2 * sn, q2r = q2 * cs + q1 * sn;
        float k1r = k1 * cs - k2 * sn, k2r = k2 * cs + k1 * sn;
        float dot = q1r * k1r + q2r * k2r;
#pragma unroll
        for (int o = 16; o; o >>= 1) dot += __shfl_xor_sync(0xffffffffu, dot, o);
        float sc = dot * 0.125f;
        float m = fmaxf(sc, 0.f);
        float es = __expf(sc - m);
        float w = es / (es + 2047.f * __expf(-m));
        xo[b][lane]      = w * v[lane];
        xo[b][lane + 32] = w * v[lane + 32];
    }
    __syncthreads();

    int e0 = cg * 64, RB0 = ks * 64;
    const float* pthr = wo + (size_t)(RB0 + rr) * DIM + e0 + 4 * c4;
    float4 w[4];
#pragma unroll
    for (int r = 0; r < 4; r++)
        w[r] = *(const float4*)(pthr + (size_t)(r * 16) * DIM);
    float a[8] = {0,0,0,0,0,0,0,0};
#pragma unroll
    for (int r = 0; r < 4; r++) {
        int d = rr + r * 16;
        float x0 = xo[0][d], x1 = xo[1][d];
        FMA8(w[r], x0, x1);
    }
    float s; int b, col;
    if (tile_reduce(a, s, b, col))
        atomicAdd(&g_h[b][e0 + col], s);
}

// ---------------- K3: rms2 + gate|up. 704 tiles ----------------------------
struct GuTF {
    const float *wg, *wu;
    const float *xs0, *xs1;
    __device__ Tile operator()(int tau) const {
        int cg = tau % 88, ks = tau / 88;
        int half = cg >= 44;
        int e0 = (cg - half * 44) * 64;
        const float* W = half ? wu : wg;
        int t = threadIdx.x;
        Tile T;
        T.p  = W + (size_t)(ks * 128 + (t >> 4)) * FFN + e0 + 4 * (t & 15);
        T.x0 = xs0 + ks * 128;
        T.x1 = xs1 + ks * 128;
        return T;
    }
};
struct GuOF {
    int par;
    __device__ void operator()(int tau, float s, int b, int col) const {
        int cg = tau % 88;
        int half = cg >= 44;
        int e0 = (cg - half * 44) * 64;
        atomicAdd(&g_gp[par][half][b][e0 + col], s);
    }
};
__global__ void __launch_bounds__(256, 2) k_gateup(const float* __restrict__ wg,
                                                   const float* __restrict__ wu,
                                                   const float* __restrict__ ln2,
                                                   int par) {
    __shared__ float xs[2][DIM];
    rms_x(ln2, xs);
    GuTF tf{wg, wu, xs[0], xs[1]};
    GuOF of{par};
    gemv_stream<FFN>(704, tf, of);
}

// ---------------- K4: silu + down. 352 tiles -------------------------------
struct DnTF {
    const float* wd;
    const float *xs0, *xs1;
    __device__ Tile operator()(int tau) const {
        int cg = tau & 15, ks = tau >> 4;
        int t = threadIdx.x;
        Tile T;
        T.p  = wd + (size_t)(ks * 128 + (t >> 4)) * DIM + cg * 64 + 4 * (t & 15);
        T.x0 = xs0 + ks * 128;
        T.x1 = xs1 + ks * 128;
        return T;
    }
};
struct DnOF {
    __device__ void operator()(int tau, float s, int b, int col) const {
        int cg = tau & 15;
        atomicAdd(&g_h[b][cg * 64 + col], s);
    }
};
__global__ void __launch_bounds__(256, 2) k_down(const float* __restrict__ wd,
                                                 int par) {
    __shared__ float xs[2][FFN];
    int t = threadIdx.x;

    if (blockIdx.x < 11) {
        float* z = (float*)g_gp[par ^ 1] + blockIdx.x * 1024;
        for (int i = t; i < 1024; i += 256) z[i] = 0.f;
    }

    for (int i = t; i < FFN; i += 256) {
        float g0 = g_gp[par][0][0][i], u0 = g_gp[par][1][0][i];
        float g1 = g_gp[par][0][1][i], u1 = g_gp[par][1][1][i];
        xs[0][i] = g0 / (1.f + __expf(-g0)) * u0;
        xs[1][i] = g1 / (1.f + __expf(-g1)) * u1;
    }
    __syncthreads();

    DnTF tf{wd, xs[0], xs[1]};
    DnOF of{};
    gemv_stream<DIM>(352, tf, of);
}

// ---------------- K5: final rms + zero logits. grid 17 ---------------------
__global__ void __launch_bounds__(256) k_final(const float* __restrict__ normw,
                                               float* __restrict__ out) {
    if (blockIdx.x < 16) {
        int base = 2 * DIM + blockIdx.x * 4000;
        for (int i = threadIdx.x; i < 4000; i += 256)
            out[base + i] = 0.f;
        return;
    }
    __shared__ float xs[2][DIM];
    rms_x(normw, xs);
    int t = threadIdx.x;
    for (int i = t; i < DIM; i += 256) {
        g_hn[0][i] = xs[0][i];
        g_hn[1][i] = xs[1][i];
        out[i]       = xs[0][i];
        out[DIM + i] = xs[1][i];
    }
}

// ---------------- K6: lm_head. 4000 tiles ----------------------------------
struct LmTF {
    const float* wlm;
    const float *xs0, *xs1;
    __device__ Tile operator()(int tau) const {
        int cg = tau % 500, ks = tau / 500;
        int t = threadIdx.x;
        Tile T;
        T.p  = wlm + (size_t)(ks * 128 + (t >> 4)) * VOCAB + cg * 64 + 4 * (t & 15);
        T.x0 = xs0 + ks * 128;
        T.x1 = xs1 + ks * 128;
        return T;
    }
};
struct LmOF {
    float* out;
    __device__ void operator()(int tau, float s, int b, int col) const {
        int cg = tau % 500;
        atomicAdd(&out[2 * DIM + (size_t)b * VOCAB + cg * 64 + col], s);
    }
};
__global__ void __launch_bounds__(256, 2) k_lmhead(const float* __restrict__ wlm,
                                                   float* __restrict__ out) {
    __shared__ float xs[2][DIM];
    int t = threadIdx.x;
    for (int i = t; i < DIM; i += 256) {
        xs[0][i] = g_hn[0][i];
        xs[1][i] = g_hn[1][i];
    }
    __syncthreads();
    LmTF tf{wlm, xs[0], xs[1]};
    LmOF of{out};
    gemv_stream<VOCAB>(4000, tf, of);
}

// ---------------- launcher ----------------
extern "C" void kernel_launch(void* const* d_in, const int* in_sizes, int n_in,
                              void* d_out, int out_size) {
    const float* emb  = (const float*)d_in[0];
    const int*   cpos = (const int*)d_in[2];
    const float* wq   = (const float*)d_in[4];
    const float* wk   = (const float*)d_in[5];
    const float* wv   = (const float*)d_in[6];
    const float* wo   = (const float*)d_in[7];
    const float* wg   = (const float*)d_in[8];
    const float* wu   = (const float*)d_in[9];
    const float* wd   = (const float*)d_in[10];
    const float* ln1  = (const float*)d_in[11];
    const float* ln2  = (const float*)d_in[12];
    const float* nw   = (const float*)d_in[13];
    const float* wlm  = (const float*)d_in[14];
    float* out = (float*)d_out;

    k_init<<<19, 1024>>>(emb);
    for (int l = 0; l < NL; l++) {
        int par = l & 1;
        size_t oqk = (size_t)l * DIM * DIM;
        size_t ogu = (size_t)l * DIM * FFN;
        k_qkv   <<<GRIDSZ, 256>>>(wq + oqk, wk + oqk, wv + oqk, ln1 + l * DIM, par);
        k_attn  <<<256,    256>>>(wo + oqk, cpos, par);
        k_gateup<<<GRIDSZ, 256>>>(wg + ogu, wu + ogu, ln2 + l * DIM, par);
        k_down  <<<GRIDSZ, 256>>>(wd + ogu, par);
    }
    k_final <<<17,     256>>>(nw, out);
    k_lmhead<<<GRIDSZ, 256>>>(wlm, out);
}

// round 11
// speedup vs baseline: 1.1634x; 1.1634x over previous
#include <cuda_runtime.h>
#include <cstdint>

#define NL   28
#define DIM  1024
#define NH   16
#define HD   64
#define FFN  2816
#define VOCAB 32000

typedef unsigned long long u64;
typedef unsigned int u32;

// ---------------- device scratch ----------------
__device__ float g_h[2][DIM];              // residual stream (RED-accumulated)
__device__ float g_qkv[2][2][3 * DIM];     // [parity][batch][q|k|v]
__device__ float g_gp[2][2][2][FFN];       // [parity][gate/up][batch][col]
__device__ float g_hn[2][DIM];             // final normed hidden

// ---------------- f32x2 / misc asm helpers ----------------
__device__ __forceinline__ void fma2(u64& d, u64 a, u64 b) {
    asm("fma.rn.f32x2 %0, %1, %2, %3;" : "=l"(d) : "l"(a), "l"(b), "l"(d));
}
__device__ __forceinline__ void add2(u64& d, u64 a) {
    asm("add.rn.f32x2 %0, %1, %2;" : "=l"(d) : "l"(d), "l"(a));
}
__device__ __forceinline__ u64 dup2(float x) {
    u64 r; asm("mov.b64 %0, {%1, %1};" : "=l"(r) : "f"(x)); return r;
}
__device__ __forceinline__ void red2(float* p, u64 a) {
    float x, y;
    asm("mov.b64 {%0, %1}, %2;" : "=f"(x), "=f"(y) : "l"(a));
    atomicAdd(p, x); atomicAdd(p + 1, y);
}
__device__ __forceinline__ u32 s2u(const void* p) {
    u32 a;
    asm("{ .reg .u64 t; cvta.to.shared.u64 t, %1; cvt.u32.u64 %0, t; }"
        : "=r"(a) : "l"(p));
    return a;
}

#define MBAR_INIT(a) \
    asm volatile("mbarrier.init.shared.b64 [%0], 1;" :: "r"(a) : "memory")
#define MBAR_EXPECT(a, n) \
    asm volatile("mbarrier.arrive.expect_tx.shared.b64 _, [%0], %1;" \
                 :: "r"(a), "r"(n) : "memory")

__device__ __forceinline__ void mbar_wait(u32 a, u32 parity) {
    u32 done;
    asm volatile(
        "{\n\t.reg .pred p;\n\t"
        "mbarrier.try_wait.parity.acquire.cta.shared::cta.b64 p, [%1], %2;\n\t"
        "selp.b32 %0, 1, 0, p;\n\t}"
        : "=r"(done) : "r"(a), "r"(parity) : "memory");
    if (!done) {
        asm volatile(
            "{\n\t.reg .pred P1;\n\t"
            "WL_%=:\n\t"
            "mbarrier.try_wait.parity.acquire.cta.shared::cta.b64 P1, [%0], %1, 0x989680;\n\t"
            "@P1 bra.uni WD_%=;\n\t"
            "bra.uni WL_%=;\n\t"
            "WD_%=:\n\t}"
            :: "r"(a), "r"(parity) : "memory");
    }
}

__device__ __forceinline__ void bulk_g2s(u32 dst, const void* src, u32 bytes, u32 mbar) {
    asm volatile(
        "cp.async.bulk.shared::cluster.global.mbarrier::complete_tx::bytes "
        "[%0], [%1], %2, [%3];"
        :: "r"(dst), "l"(src), "r"(bytes), "r"(mbar) : "memory");
}

// ---------------- TMA tile machinery ----------------
// smem layout: [0..16) mbar[2], [16..4112) xq pairs, [8192..) tile buffers.
#define XQ_OFF  16
#define BUF_OFF 8192

template<int SEG, int TR>
__device__ __forceinline__ void issue_tile(u32 mbar, u32 dst,
                                           const float* W, size_t ldb) {
    MBAR_EXPECT(mbar, SEG * TR);
    const char* s = (const char*)W;
#pragma unroll 4
    for (int r = 0; r < TR; r++)
        bulk_g2s(dst + r * SEG, s + (size_t)r * ldb, SEG, mbar);
}

template<int SEG, int TR, int NT>
__device__ __forceinline__ void start_load(char* smem, const float* W, size_t ldb) {
    u32 sb = s2u(smem);
    if (threadIdx.x == 0) { MBAR_INIT(sb); MBAR_INIT(sb + 8); }
    __syncthreads();
    if (threadIdx.x == 0) {
        issue_tile<SEG, TR>(sb, sb + BUF_OFF, W, ldb);
        if (NT > 1)
            issue_tile<SEG, TR>(sb + 8, sb + BUF_OFF + SEG * TR,
                                (const float*)((const char*)W + (size_t)TR * ldb), ldb);
    }
}

template<int COLS, int TR, int NT>
__device__ __forceinline__ void gemv_core(char* smem, const float* W, size_t ldb,
                                          u64 acc[4]) {
    constexpr int SEG = COLS * 4, TILEB = SEG * TR;
    constexpr int QUADS = COLS / 4, NRG = 256 / QUADS, RPT = TR / NRG;
    const int t = threadIdx.x;
    u32 sb = s2u(smem);
    const ulonglong2* xq = (const ulonglong2*)(smem + XQ_OFF);
    int c4 = t & (QUADS - 1), rg = t / QUADS;
    acc[0] = acc[1] = acc[2] = acc[3] = 0;
#pragma unroll
    for (int i = 0; i < NT; i++) {
        mbar_wait(sb + 8 * (i & 1), (i >> 1) & 1);
        const char* base = smem + BUF_OFF + (i & 1) * TILEB;
#pragma unroll
        for (int r = 0; r < RPT; r++) {
            int row = rg * RPT + r;
            ulonglong2 wl = *(const ulonglong2*)(base + row * SEG + c4 * 16);
            ulonglong2 x  = xq[i * TR + row];
            fma2(acc[0], wl.x, x.x);
            fma2(acc[1], wl.y, x.x);
            fma2(acc[2], wl.x, x.y);
            fma2(acc[3], wl.y, x.y);
        }
        if (i + 2 < NT) {
            __syncthreads();
            if (t == 0)
                issue_tile<SEG, TR>(sb + 8 * (i & 1), sb + BUF_OFF + (i & 1) * TILEB,
                    (const float*)((const char*)W + (size_t)(i + 2) * TR * ldb), ldb);
        }
    }
}

// cross-row-group reduce; true on rg==0 threads (t < QUADS).
template<int QUADS>
__device__ __forceinline__ bool final_reduce(char* smem, u64 acc[4]) {
    constexpr int NRG = 256 / QUADS;
    int t = threadIdx.x, c4 = t & (QUADS - 1), rg = t / QUADS;
    u64* scr = (u64*)(smem + BUF_OFF);   // tile buffers are dead by now
    __syncthreads();
    if (rg > 0) {
        u64* p = scr + ((size_t)(rg - 1) * QUADS + c4) * 4;
        p[0] = acc[0]; p[1] = acc[1]; p[2] = acc[2]; p[3] = acc[3];
    }
    __syncthreads();
    if (rg) return false;
#pragma unroll
    for (int g = 0; g < NRG - 1; g++) {
        u64* p = scr + ((size_t)g * QUADS + c4) * 4;
        add2(acc[0], p[0]); add2(acc[1], p[1]);
        add2(acc[2], p[2]); add2(acc[3], p[3]);
    }
    return true;
}

// ---------------- prologues ----------------
__device__ __forceinline__ float block_sum(float v) {
    __shared__ float sh[8];
    int lane = threadIdx.x & 31, w = threadIdx.x >> 5;
#pragma unroll
    for (int o = 16; o; o >>= 1) v += __shfl_xor_sync(0xffffffffu, v, o);
    __syncthreads();
    if (lane == 0) sh[w] = v;
    __syncthreads();
    float r = sh[0];
#pragma unroll
    for (int i = 1; i < 8; i++) r += sh[i];
    return r;
}

__device__ __forceinline__ void rms_prologue(char* smem, const float* __restrict__ gamma,
                                             int k0, int nrows) {
    ulonglong2* xq = (ulonglong2*)(smem + XQ_OFF);
    int t = threadIdx.x;
    float s0 = 0.f, s1 = 0.f;
#pragma unroll
    for (int i = t; i < DIM; i += 256) {
        float v0 = g_h[0][i], v1 = g_h[1][i];
        s0 += v0 * v0; s1 += v1 * v1;
    }
    s0 = block_sum(s0);
    s1 = block_sum(s1);
    float r0 = rsqrtf(s0 * (1.f / DIM) + 1e-5f);
    float r1 = rsqrtf(s1 * (1.f / DIM) + 1e-5f);
    if (t < nrows) {
        int k = k0 + t;
        float g = gamma[k];
        ulonglong2 v;
        v.x = dup2(g_h[0][k] * r0 * g);
        v.y = dup2(g_h[1][k] * r1 * g);
        xq[t] = v;
    }
    __syncthreads();
}

// ---------------- init ----------------
__global__ void k_init(const float* __restrict__ emb) {
    int i = blockIdx.x * blockDim.x + threadIdx.x;
    if (i < 2 * DIM) g_h[i / DIM][i % DIM] = emb[i];
    int z = i - 2 * DIM;
    if (z >= 0) {
        if (z < 2 * 3 * DIM)              ((float*)g_qkv[0])[z] = 0.f;
        else if (z < 2*3*DIM + 4*FFN)     ((float*)g_gp[0])[z - 2*3*DIM] = 0.f;
    }
}

// ---------------- K1: rms1 + QKV. grid 384 = 24cg x 16kc -------------------
__global__ void __launch_bounds__(256) k_qkv(const float* __restrict__ wq,
                                             const float* __restrict__ wk,
                                             const float* __restrict__ wv,
                                             const float* __restrict__ ln1,
                                             int par) {
    extern __shared__ char smem[];
    int bid = blockIdx.x;
    int cg = bid % 24, kc = bid / 24;
    int mat = cg >> 3, cgm = cg & 7, k0 = kc * 64;
    const float* Wm = mat == 0 ? wq : (mat == 1 ? wk : wv);
    const float* W = Wm + (size_t)k0 * DIM + cgm * 128;

    start_load<512, 64, 1>(smem, W, DIM * 4);
    rms_prologue(smem, ln1, k0, 64);

    u64 acc[4];
    gemv_core<128, 64, 1>(smem, W, DIM * 4, acc);
    if (final_reduce<32>(smem, acc)) {
        int c4 = threadIdx.x;
        float* p0 = &g_qkv[par][0][mat * DIM + cgm * 128 + c4 * 4];
        float* p1 = &g_qkv[par][1][mat * DIM + cgm * 128 + c4 * 4];
        red2(p0, acc[0]); red2(p0 + 2, acc[1]);
        red2(p1, acc[2]); red2(p1 + 2, acc[3]);
    }
}

// ---------------- K2: RoPE + attn + O. grid 256 = 16cg x 16head ------------
__global__ void __launch_bounds__(256) k_attn(const float* __restrict__ wo,
                                              const int* __restrict__ cpos,
                                              int par) {
    extern __shared__ char smem[];
    int bid = blockIdx.x;
    int cg = bid & 15, head = bid >> 4;
    const float* W = wo + (size_t)(head * 64) * DIM + cg * 64;

    start_load<256, 64, 1>(smem, W, DIM * 4);

    int t = threadIdx.x, lane = t & 31, wid = t >> 5;
    if (bid < 16) {                       // zero next-parity qkv accumulator
        float* z = (float*)g_qkv[par ^ 1] + bid * 384;
        for (int i = t; i < 384; i += 256) z[i] = 0.f;
    }

    ulonglong2* xq = (ulonglong2*)(smem + XQ_OFF);
    if (wid < 2) {
        int b = wid;
        const float* q = &g_qkv[par][b][head * HD];
        const float* k = &g_qkv[par][b][DIM + head * HD];
        const float* v = &g_qkv[par][b][2 * DIM + head * HD];
        int pos = cpos[0];
        float inv_freq = __expf(-(float)(2 * lane) * (1.f / HD) * logf(10000.f));
        float ang = (float)pos * inv_freq;
        float cs = cosf(ang), sn = sinf(ang);
        float q1 = q[lane], q2 = q[lane + 32];
        float k1 = k[lane], k2 = k[lane + 32];
        float q1r = q1 * cs - q2 * sn, q2r = q2 * cs + q1 * sn;
        float k1r = k1 * cs - k2 * sn, k2r = k2 * cs + k1 * sn;
        float dot = q1r * k1r + q2r * k2r;
#pragma unroll
        for (int o = 16; o; o >>= 1) dot += __shfl_xor_sync(0xffffffffu, dot, o);
        float sc = dot * 0.125f;
        float m = fmaxf(sc, 0.f);
        float es = __expf(sc - m);
        float w = es / (es + 2047.f * __expf(-m));
        u64 lo = dup2(w * v[lane]);
        u64 hi = dup2(w * v[lane + 32]);
        if (b == 0) { xq[lane].x = lo; xq[lane + 32].x = hi; }
        else        { xq[lane].y = lo; xq[lane + 32].y = hi; }
    }
    __syncthreads();

    u64 acc[4];
    gemv_core<64, 64, 1>(smem, W, DIM * 4, acc);
    if (final_reduce<16>(smem, acc)) {
        int c4 = threadIdx.x;
        float* p0 = &g_h[0][cg * 64 + c4 * 4];
        float* p1 = &g_h[1][cg * 64 + c4 * 4];
        red2(p0, acc[0]); red2(p0 + 2, acc[1]);
        red2(p1, acc[2]); red2(p1 + 2, acc[3]);
    }
}

// ---------------- K3: rms2 + gate|up. grid 352 = 22cg x 16kc ---------------
__global__ void __launch_bounds__(256) k_gateup(const float* __restrict__ wg,
                                                const float* __restrict__ wu,
                                                const float* __restrict__ ln2,
                                                int par) {
    extern __shared__ char smem[];
    int bid = blockIdx.x;
    int cg = bid % 22, kc = bid / 22;
    int half = cg / 11, cgm = cg % 11, k0 = kc * 64;
    const float* W = (half ? wu : wg) + (size_t)k0 * FFN + cgm * 256;

    start_load<1024, 32, 2>(smem, W, FFN * 4);
    rms_prologue(smem, ln2, k0, 64);

    u64 acc[4];
    gemv_core<256, 32, 2>(smem, W, FFN * 4, acc);
    if (final_reduce<64>(smem, acc)) {
        int c4 = threadIdx.x;
        float* p0 = &g_gp[par][half][0][cgm * 256 + c4 * 4];
        float* p1 = &g_gp[par][half][1][cgm * 256 + c4 * 4];
        red2(p0, acc[0]); red2(p0 + 2, acc[1]);
        red2(p1, acc[2]); red2(p1 + 2, acc[3]);
    }
}

// ---------------- K4: silu + down. grid 352 = 8cg x 44kc -------------------
__global__ void __launch_bounds__(256) k_down(const float* __restrict__ wd,
                                              int par) {
    extern __shared__ char smem[];
    int bid = blockIdx.x;
    int cg = bid & 7, kc = bid >> 3, k0 = kc * 64;
    const float* W = wd + (size_t)k0 * DIM + cg * 128;

    start_load<512, 64, 1>(smem, W, DIM * 4);

    int t = threadIdx.x;
    if (bid < 11) {                      // zero next-parity gate/up accumulator
        float* z = (float*)g_gp[par ^ 1] + bid * 1024;
        for (int i = t; i < 1024; i += 256) z[i] = 0.f;
    }

    ulonglong2* xq = (ulonglong2*)(smem + XQ_OFF);
    if (t < 64) {
        int k = k0 + t;
        float g0 = g_gp[par][0][0][k], u0 = g_gp[par][1][0][k];
        float g1 = g_gp[par][0][1][k], u1 = g_gp[par][1][1][k];
        ulonglong2 v;
        v.x = dup2(g0 / (1.f + __expf(-g0)) * u0);
        v.y = dup2(g1 / (1.f + __expf(-g1)) * u1);
        xq[t] = v;
    }
    __syncthreads();

    u64 acc[4];
    gemv_core<128, 64, 1>(smem, W, DIM * 4, acc);
    if (final_reduce<32>(smem, acc)) {
        int c4 = threadIdx.x;
        float* p0 = &g_h[0][cg * 128 + c4 * 4];
        float* p1 = &g_h[1][cg * 128 + c4 * 4];
        red2(p0, acc[0]); red2(p0 + 2, acc[1]);
        red2(p1, acc[2]); red2(p1 + 2, acc[3]);
    }
}

// ---------------- K5: final rms + zero logits. grid 17 ---------------------
__global__ void __launch_bounds__(256) k_final(const float* __restrict__ normw,
                                               float* __restrict__ out) {
    if (blockIdx.x < 16) {
        int base = 2 * DIM + blockIdx.x * 4000;
        for (int i = threadIdx.x; i < 4000; i += 256)
            out[base + i] = 0.f;
        return;
    }
    int t = threadIdx.x;
    float s0 = 0.f, s1 = 0.f;
#pragma unroll
    for (int i = t; i < DIM; i += 256) {
        float v0 = g_h[0][i], v1 = g_h[1][i];
        s0 += v0 * v0; s1 += v1 * v1;
    }
    s0 = block_sum(s0);
    s1 = block_sum(s1);
    float r0 = rsqrtf(s0 * (1.f / DIM) + 1e-5f);
    float r1 = rsqrtf(s1 * (1.f / DIM) + 1e-5f);
    for (int i = t; i < DIM; i += 256) {
        float g = normw[i];
        float h0 = g_h[0][i] * r0 * g;
        float h1 = g_h[1][i] * r1 * g;
        g_hn[0][i] = h0;
        g_hn[1][i] = h1;
        out[i]       = h0;
        out[DIM + i] = h1;
    }
}

// ---------------- K6: lm_head. grid 500 = 125cg x 4kc ----------------------
__global__ void __launch_bounds__(256) k_lmhead(const float* __restrict__ wlm,
                                                float* __restrict__ out) {
    extern __shared__ char smem[];
    int bid = blockIdx.x;
    int cg = bid % 125, kc = bid / 125, k0 = kc * 256;
    const float* W = wlm + (size_t)k0 * VOCAB + cg * 256;

    start_load<1024, 32, 8>(smem, W, VOCAB * 4);

    int t = threadIdx.x;
    ulonglong2* xq = (ulonglong2*)(smem + XQ_OFF);
    {
        int k = k0 + t;
        ulonglong2 v;
        v.x = dup2(g_hn[0][k]);
        v.y = dup2(g_hn[1][k]);
        xq[t] = v;
    }
    __syncthreads();

    u64 acc[4];
    gemv_core<256, 32, 8>(smem, W, VOCAB * 4, acc);
    if (final_reduce<64>(smem, acc)) {
        int c4 = threadIdx.x;
        float* p0 = out + 2 * DIM + cg * 256 + c4 * 4;
        float* p1 = out + 2 * DIM + VOCAB + cg * 256 + c4 * 4;
        red2(p0, acc[0]); red2(p0 + 2, acc[1]);
        red2(p1, acc[2]); red2(p1 + 2, acc[3]);
    }
}

// ---------------- launcher ----------------
extern "C" void kernel_launch(void* const* d_in, const int* in_sizes, int n_in,
                              void* d_out, int out_size) {
    const float* emb  = (const float*)d_in[0];
    const int*   cpos = (const int*)d_in[2];
    const float* wq   = (const float*)d_in[4];
    const float* wk   = (const float*)d_in[5];
    const float* wv   = (const float*)d_in[6];
    const float* wo   = (const float*)d_in[7];
    const float* wg   = (const float*)d_in[8];
    const float* wu   = (const float*)d_in[9];
    const float* wd   = (const float*)d_in[10];
    const float* ln1  = (const float*)d_in[11];
    const float* ln2  = (const float*)d_in[12];
    const float* nw   = (const float*)d_in[13];
    const float* wlm  = (const float*)d_in[14];
    float* out = (float*)d_out;

    const int SM_QKV = BUF_OFF + 32768;            // 1 slot, 32KB tile
    const int SM_ATT = BUF_OFF + 16384;            // 1 slot, 16KB tile
    const int SM_GU  = BUF_OFF + 2 * 32768;        // 2 slots
    const int SM_DN  = BUF_OFF + 32768;
    const int SM_LM  = BUF_OFF + 2 * 32768;

    static bool attr_done = false;
    if (!attr_done) {
        cudaFuncSetAttribute(k_qkv,    cudaFuncAttributeMaxDynamicSharedMemorySize, SM_QKV);
        cudaFuncSetAttribute(k_attn,   cudaFuncAttributeMaxDynamicSharedMemorySize, SM_ATT);
        cudaFuncSetAttribute(k_gateup, cudaFuncAttributeMaxDynamicSharedMemorySize, SM_GU);
        cudaFuncSetAttribute(k_down,   cudaFuncAttributeMaxDynamicSharedMemorySize, SM_DN);
        cudaFuncSetAttribute(k_lmhead, cudaFuncAttributeMaxDynamicSharedMemorySize, SM_LM);
        attr_done = true;
    }

    k_init<<<19, 1024>>>(emb);
    for (int l = 0; l < NL; l++) {
        int par = l & 1;
        size_t oqk = (size_t)l * DIM * DIM;
        size_t ogu = (size_t)l * DIM * FFN;
        k_qkv   <<<384, 256, SM_QKV>>>(wq + oqk, wk + oqk, wv + oqk, ln1 + l * DIM, par);
        k_attn  <<<256, 256, SM_ATT>>>(wo + oqk, cpos, par);
        k_gateup<<<352, 256, SM_GU >>>(wg + ogu, wu + ogu, ln2 + l * DIM, par);
        k_down  <<<352, 256, SM_DN >>>(wd + ogu, par);
    }
    k_final <<<17,  256>>>(nw, out);
    k_lmhead<<<500, 256, SM_LM>>>(wlm, out);
}

// round 12
// speedup vs baseline: 1.1838x; 1.0175x over previous
#include <cuda_runtime.h>
#include <cstdint>

#define NL   28
#define DIM  1024
#define NH   16
#define HD   64
#define FFN  2816
#define VOCAB 32000

typedef unsigned long long u64;
typedef unsigned int u32;

// ---------------- device scratch ----------------
__device__ float g_h[2][DIM];              // residual stream (RED-accumulated)
__device__ float g_qkv[2][2][3 * DIM];     // [parity][batch][q|k|v]
__device__ float g_gp[2][2][2][FFN];       // [parity][gate/up][batch][col]
__device__ float g_hn[2][DIM];             // final normed hidden

// ---------------- asm helpers ----------------
__device__ __forceinline__ void fma2(u64& d, u64 a, u64 b) {
    asm("fma.rn.f32x2 %0, %1, %2, %3;" : "=l"(d) : "l"(a), "l"(b), "l"(d));
}
__device__ __forceinline__ u64 dup2(float x) {
    u64 r; asm("mov.b64 %0, {%1, %1};" : "=l"(r) : "f"(x)); return r;
}
__device__ __forceinline__ void red4(float* p, u64 a01, u64 a23) {
    float ax, ay, bx, by;
    asm("mov.b64 {%0, %1}, %2;" : "=f"(ax), "=f"(ay) : "l"(a01));
    asm("mov.b64 {%0, %1}, %2;" : "=f"(bx), "=f"(by) : "l"(a23));
    asm volatile("red.global.add.v4.f32 [%0], {%1,%2,%3,%4};"
                 :: "l"(p), "f"(ax), "f"(ay), "f"(bx), "f"(by) : "memory");
}
__device__ __forceinline__ u32 s2u(const void* p) {
    u32 a;
    asm("{ .reg .u64 t; cvta.to.shared.u64 t, %1; cvt.u32.u64 %0, t; }"
        : "=r"(a) : "l"(p));
    return a;
}

#define MBAR_INIT(a) \
    asm volatile("mbarrier.init.shared.b64 [%0], 1;" :: "r"(a) : "memory")
#define MBAR_EXPECT(a, n) \
    asm volatile("mbarrier.arrive.expect_tx.shared.b64 _, [%0], %1;" \
                 :: "r"(a), "r"(n) : "memory")

__device__ __forceinline__ void mbar_wait(u32 a, u32 parity) {
    u32 done;
    asm volatile(
        "{\n\t.reg .pred p;\n\t"
        "mbarrier.try_wait.parity.acquire.cta.shared::cta.b64 p, [%1], %2;\n\t"
        "selp.b32 %0, 1, 0, p;\n\t}"
        : "=r"(done) : "r"(a), "r"(parity) : "memory");
    if (!done) {
        asm volatile(
            "{\n\t.reg .pred P1;\n\t"
            "WL_%=:\n\t"
            "mbarrier.try_wait.parity.acquire.cta.shared::cta.b64 P1, [%0], %1, 0x989680;\n\t"
            "@P1 bra.uni WD_%=;\n\t"
            "bra.uni WL_%=;\n\t"
            "WD_%=:\n\t}"
            :: "r"(a), "r"(parity) : "memory");
    }
}

__device__ __forceinline__ void bulk_g2s(u32 dst, const void* src, u32 bytes, u32 mbar) {
    asm volatile(
        "cp.async.bulk.shared::cluster.global.mbarrier::complete_tx::bytes "
        "[%0], [%1], %2, [%3];"
        :: "r"(dst), "l"(src), "r"(bytes), "r"(mbar) : "memory");
}

// ---------------- smem layout ----------------
// [0..16)   two mbarriers
// [64..2112) xq: up to 128 ulonglong2 ((x0,x0),(x1,x1)) per row
// [1536*?]  (attn scalar scratch at 2112)
// [4096..)  two tile buffers
#define XQ_OFF  64
#define WSC_OFF 2200
#define BUF_OFF 4096

template<int SEG, int NCOPY>
__device__ __forceinline__ void issue_tile(u32 mbar, u32 dst, const char* src,
                                           size_t grow) {
    MBAR_EXPECT(mbar, SEG * NCOPY);
#pragma unroll
    for (int c = 0; c < NCOPY; c++)
        bulk_g2s(dst + c * SEG, src + (size_t)c * grow, SEG, mbar);
}

template<int SEG, int NCOPY, int RPT, int NT>
__device__ __forceinline__ void start_load(char* smem, const char* W, size_t grow) {
    u32 sb = s2u(smem);
    if (threadIdx.x == 0) { MBAR_INIT(sb); MBAR_INIT(sb + 8); }
    __syncthreads();
    if (threadIdx.x == 0) {
        issue_tile<SEG, NCOPY>(sb, sb + BUF_OFF, W, grow);
        if (NT > 1)
            issue_tile<SEG, NCOPY>(sb + 8, sb + BUF_OFF + SEG * NCOPY,
                                   W + (size_t)RPT * grow, grow);
    }
}

// streaming GEMV: thread owns NF4 float4-columns (at t, t+nthr, ...) across
// ALL rows of the block; acc[f][0..3] = (b0 c01, b0 c23, b1 c01, b1 c23).
template<int ROWB, int RPT, int NT, int NF4, int SEG, int NCOPY, int NTHR>
__device__ __forceinline__ void gemv_run(char* smem, const char* W, size_t grow,
                                         int active, u64 (*acc)[4]) {
    const int t = threadIdx.x;
    u32 sb = s2u(smem);
    constexpr int TILEB = SEG * NCOPY;
    const ulonglong2* xq = (const ulonglong2*)(smem + XQ_OFF);
#pragma unroll
    for (int f = 0; f < NF4; f++)
        acc[f][0] = acc[f][1] = acc[f][2] = acc[f][3] = 0;
#pragma unroll
    for (int i = 0; i < NT; i++) {
        mbar_wait(sb + 8 * (i & 1), (i >> 1) & 1);
        const char* base = smem + BUF_OFF + (i & 1) * TILEB;
        if (t < active) {
#pragma unroll
            for (int r = 0; r < RPT; r++) {
                ulonglong2 x = xq[i * RPT + r];
#pragma unroll
                for (int f = 0; f < NF4; f++) {
                    ulonglong2 wl = *(const ulonglong2*)(base + r * ROWB +
                                                         (t + f * NTHR) * 16);
                    fma2(acc[f][0], wl.x, x.x);
                    fma2(acc[f][1], wl.y, x.x);
                    fma2(acc[f][2], wl.x, x.y);
                    fma2(acc[f][3], wl.y, x.y);
                }
            }
        }
        if (i + 2 < NT) {
            __syncthreads();
            if (t == 0)
                issue_tile<SEG, NCOPY>(sb + 8 * (i & 1),
                                       sb + BUF_OFF + (i & 1) * TILEB,
                                       W + (size_t)(i + 2) * RPT * grow, grow);
        }
    }
}

// ---------------- prologues ----------------
template<int NW>
__device__ __forceinline__ float block_sum(float v) {
    __shared__ float sh[NW];
    int lane = threadIdx.x & 31, w = threadIdx.x >> 5;
#pragma unroll
    for (int o = 16; o; o >>= 1) v += __shfl_xor_sync(0xffffffffu, v, o);
    __syncthreads();
    if (lane == 0) sh[w] = v;
    __syncthreads();
    float r = sh[0];
#pragma unroll
    for (int i = 1; i < NW; i++) r += sh[i];
    return r;
}

template<int NTHR, int NW>
__device__ __forceinline__ void rms_prologue(char* smem, const float* __restrict__ gamma,
                                             int k0, int nrows) {
    ulonglong2* xq = (ulonglong2*)(smem + XQ_OFF);
    int t = threadIdx.x;
    float s0 = 0.f, s1 = 0.f;
    for (int i = t; i < DIM; i += NTHR) {
        float v0 = g_h[0][i], v1 = g_h[1][i];
        s0 += v0 * v0; s1 += v1 * v1;
    }
    s0 = block_sum<NW>(s0);
    s1 = block_sum<NW>(s1);
    float r0 = rsqrtf(s0 * (1.f / DIM) + 1e-5f);
    float r1 = rsqrtf(s1 * (1.f / DIM) + 1e-5f);
    if (t < nrows) {
        int k = k0 + t;
        float g = gamma[k];
        ulonglong2 v;
        v.x = dup2(g_h[0][k] * r0 * g);
        v.y = dup2(g_h[1][k] * r1 * g);
        xq[t] = v;
    }
    __syncthreads();
}

// ---------------- init ----------------
__global__ void k_init(const float* __restrict__ emb) {
    int i = blockIdx.x * blockDim.x + threadIdx.x;
    if (i < 2 * DIM) g_h[i / DIM][i % DIM] = emb[i];
    int z = i - 2 * DIM;
    if (z >= 0) {
        if (z < 2 * 3 * DIM)              ((float*)g_qkv[0])[z] = 0.f;
        else if (z < 2*3*DIM + 4*FFN)     ((float*)g_gp[0])[z - 2*3*DIM] = 0.f;
    }
}

// ---------------- K1: rms1 + QKV. grid 192 = 3mat x 64rg(16 rows) ---------
__global__ void __launch_bounds__(256) k_qkv(const float* __restrict__ wq,
                                             const float* __restrict__ wk,
                                             const float* __restrict__ wv,
                                             const float* __restrict__ ln1,
                                             int par) {
    extern __shared__ char smem[];
    int bid = blockIdx.x;
    int mat = bid / 64, rg = bid % 64, k0 = rg * 16;
    const float* Wm = mat == 0 ? wq : (mat == 1 ? wk : wv);
    const char* W = (const char*)(Wm + (size_t)k0 * DIM);

    start_load<16384, 1, 4, 4>(smem, W, 4096);
    rms_prologue<256, 8>(smem, ln1, k0, 16);

    u64 acc[1][4];
    gemv_run<4096, 4, 4, 1, 16384, 1, 256>(smem, W, 4096, 256, acc);

    int t = threadIdx.x;
    red4(&g_qkv[par][0][mat * DIM + 4 * t], acc[0][0], acc[0][1]);
    red4(&g_qkv[par][1][mat * DIM + 4 * t], acc[0][2], acc[0][3]);
}

// ---------------- K2: RoPE + attn + O. grid 128 = 16head x 8rg(8 rows) ----
__global__ void __launch_bounds__(256) k_attn(const float* __restrict__ wo,
                                              const int* __restrict__ cpos,
                                              int par) {
    extern __shared__ char smem[];
    int bid = blockIdx.x;
    int head = bid >> 3, rg = bid & 7;
    const char* W = (const char*)(wo + (size_t)(head * 64 + rg * 8) * DIM);

    start_load<16384, 1, 4, 2>(smem, W, 4096);

    int t = threadIdx.x, lane = t & 31, wid = t >> 5;
    if (bid < 16) {                       // zero next-parity qkv accumulator
        float* z = (float*)g_qkv[par ^ 1] + bid * 384;
        for (int i = t; i < 384; i += 256) z[i] = 0.f;
    }

    float* wsc = (float*)(smem + WSC_OFF);
    if (wid < 2) {
        int b = wid;
        const float* q = &g_qkv[par][b][head * HD];
        const float* k = &g_qkv[par][b][DIM + head * HD];
        int pos = cpos[0];
        float inv_freq = __expf(-(float)(2 * lane) * (1.f / HD) * logf(10000.f));
        float ang = (float)pos * inv_freq;
        float cs = cosf(ang), sn = sinf(ang);
        float q1 = q[lane], q2 = q[lane + 32];
        float k1 = k[lane], k2 = k[lane + 32];
        float q1r = q1 * cs - q2 * sn, q2r = q2 * cs + q1 * sn;
        float k1r = k1 * cs - k2 * sn, k2r = k2 * cs + k1 * sn;
        float dot = q1r * k1r + q2r * k2r;
#pragma unroll
        for (int o = 16; o; o >>= 1) dot += __shfl_xor_sync(0xffffffffu, dot, o);
        float sc = dot * 0.125f;
        float m = fmaxf(sc, 0.f);
        float es = __expf(sc - m);
        if (lane == 0) wsc[b] = es / (es + 2047.f * __expf(-m));
    }
    __syncthreads();
    ulonglong2* xq = (ulonglong2*)(smem + XQ_OFF);
    if (t < 8) {
        int r = rg * 8 + t;
        ulonglong2 v;
        v.x = dup2(wsc[0] * g_qkv[par][0][2 * DIM + head * HD + r]);
        v.y = dup2(wsc[1] * g_qkv[par][1][2 * DIM + head * HD + r]);
        xq[t] = v;
    }
    __syncthreads();

    u64 acc[1][4];
    gemv_run<4096, 4, 2, 1, 16384, 1, 256>(smem, W, 4096, 256, acc);

    red4(&g_h[0][4 * t], acc[0][0], acc[0][1]);
    red4(&g_h[1][4 * t], acc[0][2], acc[0][3]);
}

// ---------------- K3: rms2 + gate|up. grid 256 = 2half x 128rg(8 rows) ----
__global__ void __launch_bounds__(352) k_gateup(const float* __restrict__ wg,
                                                const float* __restrict__ wu,
                                                const float* __restrict__ ln2,
                                                int par) {
    extern __shared__ char smem[];
    int bid = blockIdx.x;
    int half = bid >> 7, rg = bid & 127, k0 = rg * 8;
    const char* W = (const char*)((half ? wu : wg) + (size_t)k0 * FFN);

    start_load<45056, 1, 4, 2>(smem, W, 11264);
    rms_prologue<352, 11>(smem, ln2, k0, 8);

    u64 acc[2][4];
    gemv_run<11264, 4, 2, 2, 45056, 1, 352>(smem, W, 11264, 352, acc);

    int t = threadIdx.x;
#pragma unroll
    for (int f = 0; f < 2; f++) {
        int col = 4 * (t + f * 352);
        red4(&g_gp[par][half][0][col], acc[f][0], acc[f][1]);
        red4(&g_gp[par][half][1][col], acc[f][2], acc[f][3]);
    }
}

// ---------------- K4: silu + down. grid 176 = 176rg(16 rows) --------------
__global__ void __launch_bounds__(256) k_down(const float* __restrict__ wd,
                                              int par) {
    extern __shared__ char smem[];
    int bid = blockIdx.x;
    int k0 = bid * 16;
    const char* W = (const char*)(wd + (size_t)k0 * DIM);

    start_load<16384, 1, 4, 4>(smem, W, 4096);

    int t = threadIdx.x;
    if (bid < 11) {                      // zero next-parity gate/up accumulator
        float* z = (float*)g_gp[par ^ 1] + bid * 1024;
        for (int i = t; i < 1024; i += 256) z[i] = 0.f;
    }

    ulonglong2* xq = (ulonglong2*)(smem + XQ_OFF);
    if (t < 16) {
        int k = k0 + t;
        float g0 = g_gp[par][0][0][k], u0 = g_gp[par][1][0][k];
        float g1 = g_gp[par][0][1][k], u1 = g_gp[par][1][1][k];
        ulonglong2 v;
        v.x = dup2(g0 / (1.f + __expf(-g0)) * u0);
        v.y = dup2(g1 / (1.f + __expf(-g1)) * u1);
        xq[t] = v;
    }
    __syncthreads();

    u64 acc[1][4];
    gemv_run<4096, 4, 4, 1, 16384, 1, 256>(smem, W, 4096, 256, acc);

    red4(&g_h[0][4 * t], acc[0][0], acc[0][1]);
    red4(&g_h[1][4 * t], acc[0][2], acc[0][3]);
}

// ---------------- K5: final rms + zero logits. grid 17 ---------------------
__global__ void __launch_bounds__(256) k_final(const float* __restrict__ normw,
                                               float* __restrict__ out) {
    if (blockIdx.x < 16) {
        int base = 2 * DIM + blockIdx.x * 4000;
        for (int i = threadIdx.x; i < 4000; i += 256)
            out[base + i] = 0.f;
        return;
    }
    int t = threadIdx.x;
    float s0 = 0.f, s1 = 0.f;
    for (int i = t; i < DIM; i += 256) {
        float v0 = g_h[0][i], v1 = g_h[1][i];
        s0 += v0 * v0; s1 += v1 * v1;
    }
    s0 = block_sum<8>(s0);
    s1 = block_sum<8>(s1);
    float r0 = rsqrtf(s0 * (1.f / DIM) + 1e-5f);
    float r1 = rsqrtf(s1 * (1.f / DIM) + 1e-5f);
    for (int i = t; i < DIM; i += 256) {
        float g = normw[i];
        float h0 = g_h[0][i] * r0 * g;
        float h1 = g_h[1][i] * r1 * g;
        g_hn[0][i] = h0;
        g_hn[1][i] = h1;
        out[i]       = h0;
        out[DIM + i] = h1;
    }
}

// ---------------- K6: lm_head. grid 256 = 32chunk x 8rg(128 rows) ----------
__global__ void __launch_bounds__(256) k_lmhead(const float* __restrict__ wlm,
                                                float* __restrict__ out) {
    extern __shared__ char smem[];
    int bid = blockIdx.x;
    int chunk = bid & 31, rg = bid >> 5, k0 = rg * 128;
    const char* W = (const char*)(wlm + (size_t)k0 * VOCAB + chunk * 1000);

    start_load<4000, 8, 8, 16>(smem, W, 128000);

    int t = threadIdx.x;
    ulonglong2* xq = (ulonglong2*)(smem + XQ_OFF);
    if (t < 128) {
        int k = k0 + t;
        ulonglong2 v;
        v.x = dup2(g_hn[0][k]);
        v.y = dup2(g_hn[1][k]);
        xq[t] = v;
    }
    __syncthreads();

    u64 acc[1][4];
    gemv_run<4000, 8, 16, 1, 4000, 8, 256>(smem, W, 128000, 250, acc);

    if (t < 250) {
        int col = chunk * 1000 + 4 * t;
        red4(out + 2 * DIM + col,         acc[0][0], acc[0][1]);
        red4(out + 2 * DIM + VOCAB + col, acc[0][2], acc[0][3]);
    }
}

// ---------------- launcher ----------------
extern "C" void kernel_launch(void* const* d_in, const int* in_sizes, int n_in,
                              void* d_out, int out_size) {
    const float* emb  = (const float*)d_in[0];
    const int*   cpos = (const int*)d_in[2];
    const float* wq   = (const float*)d_in[4];
    const float* wk   = (const float*)d_in[5];
    const float* wv   = (const float*)d_in[6];
    const float* wo   = (const float*)d_in[7];
    const float* wg   = (const float*)d_in[8];
    const float* wu   = (const float*)d_in[9];
    const float* wd   = (const float*)d_in[10];
    const float* ln1  = (const float*)d_in[11];
    const float* ln2  = (const float*)d_in[12];
    const float* nw   = (const float*)d_in[13];
    const float* wlm  = (const float*)d_in[14];
    float* out = (float*)d_out;

    const int SM_QKV = BUF_OFF + 2 * 16384;   // 36864
    const int SM_ATT = BUF_OFF + 2 * 16384;
    const int SM_GU  = BUF_OFF + 2 * 45056;   // 94208
    const int SM_DN  = BUF_OFF + 2 * 16384;
    const int SM_LM  = BUF_OFF + 2 * 32000;   // 68096

    static bool attr_done = false;
    if (!attr_done) {
        cudaFuncSetAttribute(k_qkv,    cudaFuncAttributeMaxDynamicSharedMemorySize, SM_QKV);
        cudaFuncSetAttribute(k_attn,   cudaFuncAttributeMaxDynamicSharedMemorySize, SM_ATT);
        cudaFuncSetAttribute(k_gateup, cudaFuncAttributeMaxDynamicSharedMemorySize, SM_GU);
        cudaFuncSetAttribute(k_down,   cudaFuncAttributeMaxDynamicSharedMemorySize, SM_DN);
        cudaFuncSetAttribute(k_lmhead, cudaFuncAttributeMaxDynamicSharedMemorySize, SM_LM);
        attr_done = true;
    }

    k_init<<<19, 1024>>>(emb);
    for (int l = 0; l < NL; l++) {
        int par = l & 1;
        size_t oqk = (size_t)l * DIM * DIM;
        size_t ogu = (size_t)l * DIM * FFN;
        k_qkv   <<<192, 256, SM_QKV>>>(wq + oqk, wk + oqk, wv + oqk, ln1 + l * DIM, par);
        k_attn  <<<128, 256, SM_ATT>>>(wo + oqk, cpos, par);
        k_gateup<<<256, 352, SM_GU >>>(wg + ogu, wu + ogu, ln2 + l * DIM, par);
        k_down  <<<176, 256, SM_DN >>>(wd + ogu, par);
    }
    k_final <<<17,  256>>>(nw, out);
    k_lmhead<<<256, 256, SM_LM>>>(wlm, out);
}